// round 14
// baseline (speedup 1.0000x reference)
#include <cuda_runtime.h>
#include <cuda_bf16.h>
#include <cstdint>

#define S_LEN 8192
#define EDIM  64
#define BM    128
#define BN    128
#define NRB   (S_LEN / BM)      // 64 row blocks
#define NTILES_RB 64            // 64 key tiles per row block (full 8192 keys)
#define TOT_UNITS (NRB * NTILES_RB)   // 4096 work units
#define FA_GRID 148             // one CTA per SM, single wave
#define CONV_BLOCKS 64
#define CONV_W2 (S_LEN - 1)
#define CONV_H2 (EDIM - 1)
#define NCOMBINE (NRB * 8)      // 512 combine CTAs

#define ROWB  144               // padded row stride bytes (64 bf16 + 8 pad)
#define TILEB (128 * ROWB)      // 18432 B per tile buffer
#define SMEM_TOTAL (4 * TILEB)  // 73728 B (double-buffered K,V)

// proj kernel smem: xb[128][144B] bf16 + wb[64][144B] bf16 + bs[64] f32
#define PROJ_ROWS 128
#define PROJ_XB   (PROJ_ROWS * ROWB)          // 18432
#define PROJ_WB   (EDIM * ROWB)               // 9216
#define PROJ_SMEM (PROJ_XB + PROJ_WB + 256)   // 27904 B

// ---------------- device scratch ----------------
__device__ __nv_bfloat16 g_q[S_LEN * EDIM];
__device__ __nv_bfloat16 g_k[S_LEN * EDIM];
__device__ __nv_bfloat16 g_v[S_LEN * EDIM];
__device__ float g_O[NRB][BM][EDIM];   // accumulated numerators (atomicAdd)
__device__ float g_l[NRB][BM];         // accumulated denominators (atomicAdd)
__device__ float g_final[EDIM];
__device__ float g_sig[CONV_BLOCKS];
__device__ unsigned int g_ticket;

// ---------------- PTX helpers (generic sm_80+ features only) ----------------
__device__ __forceinline__ uint32_t smem_u32(const void* p) {
    uint32_t a;
    asm("{ .reg .u64 t; cvta.to.shared.u64 t, %1; cvt.u32.u64 %0, t; }" : "=r"(a) : "l"(p));
    return a;
}
__device__ __forceinline__ void cp16(uint32_t dst, const void* src) {
    asm volatile("cp.async.cg.shared.global [%0], [%1], 16;" :: "r"(dst), "l"(src));
}
#define CP_COMMIT() asm volatile("cp.async.commit_group;" ::: "memory")
#define CP_WAIT0()  asm volatile("cp.async.wait_group 0;" ::: "memory")

__device__ __forceinline__ void ldsm4(uint32_t* r, uint32_t a) {
    asm volatile("ldmatrix.sync.aligned.m8n8.x4.shared.b16 {%0,%1,%2,%3}, [%4];"
                 : "=r"(r[0]), "=r"(r[1]), "=r"(r[2]), "=r"(r[3]) : "r"(a));
}
__device__ __forceinline__ void ldsm4t(uint32_t* r, uint32_t a) {
    asm volatile("ldmatrix.sync.aligned.m8n8.x4.trans.shared.b16 {%0,%1,%2,%3}, [%4];"
                 : "=r"(r[0]), "=r"(r[1]), "=r"(r[2]), "=r"(r[3]) : "r"(a));
}
__device__ __forceinline__ void mma_bf16(float* d, const uint32_t* a, const uint32_t* b) {
    asm volatile("mma.sync.aligned.m16n8k16.row.col.f32.bf16.bf16.f32 "
                 "{%0,%1,%2,%3}, {%4,%5,%6,%7}, {%8,%9}, {%0,%1,%2,%3};"
                 : "+f"(d[0]), "+f"(d[1]), "+f"(d[2]), "+f"(d[3])
                 : "r"(a[0]), "r"(a[1]), "r"(a[2]), "r"(a[3]), "r"(b[0]), "r"(b[1]));
}
__device__ __forceinline__ uint32_t pack_bf16x2(float lo, float hi) {
    uint32_t r;
    asm("cvt.rn.satfinite.bf16x2.f32 %0, %1, %2;" : "=r"(r) : "f"(hi), "f"(lo));
    return r;
}

// ---------------- kernel 1: HMMA Q/K/V projection (+conv in y==3, zeroing) ----------------
__global__ void projconv_kernel(const float* __restrict__ x,
                                const float* __restrict__ Wq, const float* __restrict__ bq,
                                const float* __restrict__ Wk, const float* __restrict__ bk,
                                const float* __restrict__ Wv, const float* __restrict__ bv,
                                const float* __restrict__ cw, const float* __restrict__ cb) {
    extern __shared__ char psm[];
    const int which = blockIdx.y;
    const int tid = threadIdx.x;

    if (which == 3) {
        // zero accumulators used later in the stream
        const float4 z4 = make_float4(0.f, 0.f, 0.f, 0.f);
        float4* pO = (float4*)g_O;
        for (int i = blockIdx.x * 256 + tid; i < (NRB * BM * EDIM) / 4; i += CONV_BLOCKS * 256)
            pO[i] = z4;
        float4* pL = (float4*)g_l;
        for (int i = blockIdx.x * 256 + tid; i < (NRB * BM) / 4; i += CONV_BLOCKS * 256)
            pL[i] = z4;
        if (blockIdx.x == 0) {
            if (tid < EDIM) g_final[tid] = 0.f;
            if (tid == 64) g_ticket = 0u;
        }

        // ---- conv 2x2 + sigmoid partial sums ----
        const float w00 = cw[0], w01 = cw[1], w10 = cw[2], w11 = cw[3];
        const float bias = cb[0];
        const int total = CONV_H2 * CONV_W2;

        float acc = 0.f;
        for (int n = blockIdx.x * 256 + tid; n < total; n += CONV_BLOCKS * 256) {
            const int i = n % CONV_H2;
            const int j = n / CONV_H2;
            const float z = w00 * x[j * EDIM + i]
                          + w01 * x[(j + 1) * EDIM + i]
                          + w10 * x[j * EDIM + i + 1]
                          + w11 * x[(j + 1) * EDIM + i + 1]
                          + bias;
            acc += 1.f / (1.f + __expf(-z));
        }
        float* red = (float*)psm;
        red[tid] = acc;
        __syncthreads();
        for (int s2 = 128; s2 > 0; s2 >>= 1) {
            if (tid < s2) red[tid] += red[tid + s2];
            __syncthreads();
        }
        if (tid == 0) g_sig[blockIdx.x] = red[0];
        return;
    }

    // ---- HMMA projection: 128 rows per CTA ----
    char* xb = psm;                     // [128][144B] bf16 rows
    char* wb = psm + PROJ_XB;           // [64][144B]  bf16 rows (W: rows=f, cols=e)
    float* bs = (float*)(psm + PROJ_XB + PROJ_WB);

    const float* W = (which == 0) ? Wq : (which == 1) ? Wk : Wv;
    const float* b = (which == 0) ? bq : (which == 1) ? bk : bv;
    __nv_bfloat16* dst = (which == 0) ? g_q : (which == 1) ? g_k : g_v;

    const int r0 = blockIdx.x * PROJ_ROWS;
    const uint32_t smb = smem_u32(psm);

    // stage x tile -> bf16 smem (8 floats -> 16B bf16 per group)
#pragma unroll
    for (int it = 0; it < 4; it++) {
        const int n = tid + it * 256;            // 1024 groups
        const int row = n >> 3, seg = n & 7;
        const float4 a0 = *(const float4*)&x[(r0 + row) * EDIM + seg * 8];
        const float4 a1 = *(const float4*)&x[(r0 + row) * EDIM + seg * 8 + 4];
        uint4 u;
        u.x = pack_bf16x2(a0.x, a0.y); u.y = pack_bf16x2(a0.z, a0.w);
        u.z = pack_bf16x2(a1.x, a1.y); u.w = pack_bf16x2(a1.z, a1.w);
        *(uint4*)(xb + row * ROWB + seg * 16) = u;
    }
    // stage W -> bf16 smem
#pragma unroll
    for (int it = 0; it < 2; it++) {
        const int n = tid + it * 256;            // 512 groups
        const int row = n >> 3, seg = n & 7;
        const float4 a0 = *(const float4*)&W[row * EDIM + seg * 8];
        const float4 a1 = *(const float4*)&W[row * EDIM + seg * 8 + 4];
        uint4 u;
        u.x = pack_bf16x2(a0.x, a0.y); u.y = pack_bf16x2(a0.z, a0.w);
        u.z = pack_bf16x2(a1.x, a1.y); u.w = pack_bf16x2(a1.z, a1.w);
        *(uint4*)(wb + row * ROWB + seg * 16) = u;
    }
    if (tid < EDIM) bs[tid] = b[tid];
    __syncthreads();

    const int wid = tid >> 5;
    const int lid = tid & 31;
    const int lr  = (lid & 7) + ((lid >> 3) & 1) * 8;
    const int lc  = ((lid >> 4) & 1) * 8;
    const int i2  = lid & 3;

    // A frags: 16 rows of x per warp
    uint32_t qa[4][4];
    {
        const uint32_t addrA = smb + (16 * wid + lr) * ROWB + lc * 2;
#pragma unroll
        for (int kc = 0; kc < 4; kc++) ldsm4(qa[kc], addrA + kc * 32);
    }

    // C frags init with bias
    float acc[8][4];
#pragma unroll
    for (int nt = 0; nt < 8; nt++) {
        const float b0 = bs[8 * nt + 2 * i2];
        const float b1 = bs[8 * nt + 2 * i2 + 1];
        acc[nt][0] = b0; acc[nt][1] = b1; acc[nt][2] = b0; acc[nt][3] = b1;
    }

    // B frags from W via trans-ldmatrix (rows=f=k, cols=e=n)
    const uint32_t addrW = smb + PROJ_XB + lr * ROWB + lc * 2;
#pragma unroll
    for (int kc = 0; kc < 4; kc++) {
        uint32_t wf[8][2];
#pragma unroll
        for (int p = 0; p < 4; p++) ldsm4t(&wf[2 * p][0], addrW + kc * (16 * ROWB) + p * 32);
#pragma unroll
        for (int nt = 0; nt < 8; nt++) mma_bf16(acc[nt], qa[kc], wf[nt]);
    }

    // store packed bf16 results
    const int g = lid >> 2;
    const int gr0 = r0 + 16 * wid + g;
    const int gr1 = gr0 + 8;
#pragma unroll
    for (int nt = 0; nt < 8; nt++) {
        const int e = 8 * nt + 2 * i2;
        *(uint32_t*)&dst[gr0 * EDIM + e] = pack_bf16x2(acc[nt][0], acc[nt][1]);
        *(uint32_t*)&dst[gr1 * EDIM + e] = pack_bf16x2(acc[nt][2], acc[nt][3]);
    }
}

// ---------------- async tile loader: 128 rows x 64 bf16, padded rows ----------------
__device__ __forceinline__ void load_part(uint32_t dst, const __nv_bfloat16* __restrict__ src,
                                          int row0, int tid) {
#pragma unroll
    for (int it = 0; it < 4; it++) {
        const int n = tid + it * 256;
        const int j = n >> 3, seg = n & 7;
        cp16(dst + j * ROWB + seg * 16, src + (row0 + j) * EDIM + seg * 8);
    }
}

// ---------------- kernel 2: HMMA flash attention (flattened work units, 148 CTAs) ----------------
__global__ void __launch_bounds__(256, 1) fa_kernel() {
    extern __shared__ char sm[];
    const uint32_t smb = smem_u32(sm);
    const int tid = threadIdx.x;
    const int wid = tid >> 5;
    const int lid = tid & 31;

    // lane offset patterns for ldmatrix address generation
    const int lr  = (lid & 7) + ((lid >> 3) & 1) * 8;   // A / V(trans) row pattern
    const int lc  = ((lid >> 4) & 1) * 8;               // A / V(trans) col pattern
    const int lr2 = (lid & 7) + ((lid >> 4) & 1) * 8;   // K(B) row pattern
    const int lc2 = ((lid >> 3) & 1) * 8;               // K(B) col pattern

    const int g  = lid >> 2;
    const int i2 = lid & 3;

    // contiguous unit range for this CTA
    int u        = (int)(((long long)blockIdx.x * TOT_UNITS) / FA_GRID);
    const int u1 = (int)(((long long)(blockIdx.x + 1) * TOT_UNITS) / FA_GRID);

    while (u < u1) {
        const int rb   = u >> 6;                       // row block
        const int t0   = u & 63;                       // first tile in this segment
        const int tend = min(u1 - (rb << 6), NTILES_RB);
        const int i0   = rb * BM;

        // ---- stage Q for this rb, build persistent A-frags ----
        __syncthreads();   // prior segment's smem reads complete
#pragma unroll
        for (int it = 0; it < 4; it++) {
            const int n = tid + it * 256;
            const int j = n >> 3, seg = n & 7;
            *(uint4*)(sm + j * ROWB + seg * 16) = *(const uint4*)(g_q + (i0 + j) * EDIM + seg * 8);
        }
        __syncthreads();

        uint32_t qh[4][4];
        {
            const uint32_t addrA = smb + (16 * wid + lr) * ROWB + lc * 2;
#pragma unroll
            for (int kc = 0; kc < 4; kc++) ldsm4(qh[kc], addrA + kc * 32);
        }
        __syncthreads();

        // ---- prologue: prefetch first tile into buffer 0 ----
        load_part(smb + 0 * TILEB, g_k, t0 * BN, tid);
        load_part(smb + 1 * TILEB, g_v, t0 * BN, tid);
        CP_COMMIT();

        float Oacc[8][4];
#pragma unroll
        for (int i = 0; i < 8; i++)
#pragma unroll
            for (int j = 0; j < 4; j++) Oacc[i][j] = 0.f;
        float l0 = 0.f, l1 = 0.f;

        int buf = 0;
        for (int t = t0; t < tend; t++, buf ^= 1) {
            CP_WAIT0();
            __syncthreads();

            if (t + 1 < tend) {  // prefetch next tile into other buffer
                const uint32_t nb = smb + (buf ^ 1) * 2 * TILEB;
                load_part(nb + 0 * TILEB, g_k, (t + 1) * BN, tid);
                load_part(nb + 1 * TILEB, g_v, (t + 1) * BN, tid);
                CP_COMMIT();
            }

            const uint32_t cb = smb + buf * 2 * TILEB;

            // ---- GEMM1: S(16x128 per warp) = Q * K^T ----
            float sacc[16][4];
#pragma unroll
            for (int i = 0; i < 16; i++)
#pragma unroll
                for (int j = 0; j < 4; j++) sacc[i][j] = 0.f;

            const uint32_t addrK = cb + lr2 * ROWB + lc2 * 2;
#pragma unroll
            for (int kc = 0; kc < 4; kc++) {
                uint32_t kb[16][2];
#pragma unroll
                for (int p = 0; p < 8; p++) ldsm4(&kb[2 * p][0], addrK + p * (16 * ROWB) + kc * 32);
#pragma unroll
                for (int nt = 0; nt < 16; nt++) mma_bf16(sacc[nt], qh[kc], kb[nt]);
            }

            // ---- softmax epilogue (no max, no rescale): P = exp(S/8), in-register ----
            uint32_t pa[8][4];
#pragma unroll
            for (int nt = 0; nt < 16; nt++) {
                const float p0 = __expf(sacc[nt][0] * 0.125f);
                const float p1 = __expf(sacc[nt][1] * 0.125f);
                const float p2 = __expf(sacc[nt][2] * 0.125f);
                const float p3 = __expf(sacc[nt][3] * 0.125f);
                l0 += p0 + p1;
                l1 += p2 + p3;
                pa[nt >> 1][(nt & 1) * 2 + 0] = pack_bf16x2(p0, p1);
                pa[nt >> 1][(nt & 1) * 2 + 1] = pack_bf16x2(p2, p3);
            }

            // ---- GEMM2: O(16x64 per warp) += P * V ----
            const uint32_t addrV = cb + TILEB + lr * ROWB + lc * 2;
#pragma unroll
            for (int ks = 0; ks < 8; ks++) {
                uint32_t vb[8][2];
#pragma unroll
                for (int p = 0; p < 4; p++) ldsm4t(&vb[2 * p][0], addrV + ks * (16 * ROWB) + p * 32);
#pragma unroll
                for (int nt = 0; nt < 8; nt++) mma_bf16(Oacc[nt], pa[ks], vb[nt]);
            }
        }

        // ---- flush segment partials into per-rb accumulators ----
        const int r0 = 16 * wid + g;
        const int r1 = r0 + 8;
#pragma unroll
        for (int nt = 0; nt < 8; nt++) {
            const int e = 8 * nt + 2 * i2;
            atomicAdd(&g_O[rb][r0][e],     Oacc[nt][0]);
            atomicAdd(&g_O[rb][r0][e + 1], Oacc[nt][1]);
            atomicAdd(&g_O[rb][r1][e],     Oacc[nt][2]);
            atomicAdd(&g_O[rb][r1][e + 1], Oacc[nt][3]);
        }
        l0 += __shfl_xor_sync(0xFFFFFFFF, l0, 1);
        l0 += __shfl_xor_sync(0xFFFFFFFF, l0, 2);
        l1 += __shfl_xor_sync(0xFFFFFFFF, l1, 1);
        l1 += __shfl_xor_sync(0xFFFFFFFF, l1, 2);
        if (i2 == 0) {
            atomicAdd(&g_l[rb][r0], l0);
            atomicAdd(&g_l[rb][r1], l1);
        }

        u = (rb << 6) + tend;
    }
}

// ---------------- kernel 3: normalize + column-reduce + (last CTA) final projection ----------------
__global__ void combine_kernel(const float* __restrict__ Wp,
                               const float* __restrict__ bp,
                               float* __restrict__ out) {
    __shared__ float pool[EDIM];
    __shared__ unsigned int rank;
    const int rb  = blockIdx.x;       // 0..63
    const int grp = blockIdx.y;       // 0..7 (16 rows each)
    const int tid = threadIdx.x;      // 256
    const int e = tid & 63;
    const int rg = tid >> 6;          // 0..3
    if (tid < EDIM) pool[tid] = 0.f;
    __syncthreads();

    float acc = 0.f;
#pragma unroll
    for (int jj = 0; jj < 4; jj++) {
        const int row = grp * 16 + rg * 4 + jj;
        acc += g_O[rb][row][e] * (1.f / g_l[rb][row]);
    }
    atomicAdd(&pool[e], acc);
    __syncthreads();
    if (tid < EDIM) atomicAdd(&g_final[tid], pool[tid]);

    // ---- last-CTA final projection (atomic ticket) ----
    __threadfence();
    if (tid == 0) rank = atomicAdd(&g_ticket, 1u);
    __syncthreads();
    if (rank == NCOMBINE - 1) {
        __threadfence();
        __shared__ float red[256];
        __shared__ float ps[EDIM];
        red[tid] = (tid < CONV_BLOCKS) ? g_sig[tid] : 0.f;
        if (tid < EDIM) ps[tid] = g_final[tid];
        __syncthreads();
        for (int s2 = 128; s2 > 0; s2 >>= 1) {
            if (tid < s2) red[tid] += red[tid + s2];
            __syncthreads();
        }
        if (tid < 4) {
            const float cf = red[0] / (float)(CONV_H2 * CONV_W2);
            const float sc = cf * (1.f / (float)S_LEN);
            float o = bp[tid];
#pragma unroll 8
            for (int k = 0; k < EDIM; k++)
                o += ps[k] * sc * Wp[k * 4 + tid];
            out[tid] = o;
        }
    }
}

// ---------------- launcher ----------------
extern "C" void kernel_launch(void* const* d_in, const int* in_sizes, int n_in,
                              void* d_out, int out_size) {
    const float* x      = (const float*)d_in[0];
    const float* conv_w = (const float*)d_in[1];
    const float* conv_b = (const float*)d_in[2];
    const float* Wq     = (const float*)d_in[3];
    const float* bq     = (const float*)d_in[4];
    const float* Wk     = (const float*)d_in[5];
    const float* bk     = (const float*)d_in[6];
    const float* Wv     = (const float*)d_in[7];
    const float* bv     = (const float*)d_in[8];
    const float* Wp     = (const float*)d_in[9];
    const float* bp     = (const float*)d_in[10];
    float* out = (float*)d_out;

    cudaFuncSetAttribute(fa_kernel, cudaFuncAttributeMaxDynamicSharedMemorySize, SMEM_TOTAL);
    cudaFuncSetAttribute(projconv_kernel, cudaFuncAttributeMaxDynamicSharedMemorySize, PROJ_SMEM);

    projconv_kernel<<<dim3(S_LEN / PROJ_ROWS, 4), 256, PROJ_SMEM>>>(
        x, Wq, bq, Wk, bk, Wv, bv, conv_w, conv_b);
    fa_kernel<<<FA_GRID, 256, SMEM_TOTAL>>>();
    combine_kernel<<<dim3(NRB, 8), 256>>>(Wp, bp, out);
}

// round 16
// speedup vs baseline: 1.4815x; 1.4815x over previous
#include <cuda_runtime.h>
#include <cuda_bf16.h>
#include <cstdint>

#define S_LEN 8192
#define EDIM  64
#define BM    128
#define BN    128
#define NRB   (S_LEN / BM)      // 64 row blocks
#define NCTA  (NRB * 2)         // 128 CTAs (x2 key halves)
#define KHALF (S_LEN / 2)       // 4096
#define NTILE (KHALF / BN)      // 32 key tiles per CTA
#define CONV_BLOCKS 64
#define CONV_W2 (S_LEN - 1)
#define CONV_H2 (EDIM - 1)
#define NCOMBINE (NRB * 8)      // 512 combine CTAs

#define ROWB  144               // padded row stride bytes (64 bf16 + 8 pad)
#define TILEB (128 * ROWB)      // 18432 B per tile buffer
#define SMEM_TOTAL (4 * TILEB)  // 73728 B (double-buffered K,V)

// Q pre-scale: 0.125 (1/sqrt(E)) * log2(e), so P = exp2(S') with S' = Qs K^T
#define QSCALE 0.18033688f

// proj kernel smem: xb[128][144B] bf16 + wb[64][144B] bf16 + bs[64] f32
#define PROJ_ROWS 128
#define PROJ_XB   (PROJ_ROWS * ROWB)          // 18432
#define PROJ_WB   (EDIM * ROWB)               // 9216
#define PROJ_SMEM (PROJ_XB + PROJ_WB + 256)   // 27904 B

// ---------------- device scratch ----------------
__device__ __nv_bfloat16 g_q[S_LEN * EDIM];
__device__ __nv_bfloat16 g_k[S_LEN * EDIM];
__device__ __nv_bfloat16 g_v[S_LEN * EDIM];
__device__ float g_O[NCTA][BM][EDIM];
__device__ float g_l[NCTA][BM];
__device__ float g_final[EDIM];
__device__ float g_sig[CONV_BLOCKS];
__device__ unsigned int g_ticket;

// ---------------- PTX helpers (generic sm_80+ features only) ----------------
__device__ __forceinline__ uint32_t smem_u32(const void* p) {
    uint32_t a;
    asm("{ .reg .u64 t; cvta.to.shared.u64 t, %1; cvt.u32.u64 %0, t; }" : "=r"(a) : "l"(p));
    return a;
}
__device__ __forceinline__ void cp16(uint32_t dst, const void* src) {
    asm volatile("cp.async.cg.shared.global [%0], [%1], 16;" :: "r"(dst), "l"(src));
}
#define CP_COMMIT() asm volatile("cp.async.commit_group;" ::: "memory")
#define CP_WAIT0()  asm volatile("cp.async.wait_group 0;" ::: "memory")

__device__ __forceinline__ void ldsm4(uint32_t* r, uint32_t a) {
    asm volatile("ldmatrix.sync.aligned.m8n8.x4.shared.b16 {%0,%1,%2,%3}, [%4];"
                 : "=r"(r[0]), "=r"(r[1]), "=r"(r[2]), "=r"(r[3]) : "r"(a));
}
__device__ __forceinline__ void ldsm4t(uint32_t* r, uint32_t a) {
    asm volatile("ldmatrix.sync.aligned.m8n8.x4.trans.shared.b16 {%0,%1,%2,%3}, [%4];"
                 : "=r"(r[0]), "=r"(r[1]), "=r"(r[2]), "=r"(r[3]) : "r"(a));
}
__device__ __forceinline__ void mma_bf16(float* d, const uint32_t* a, const uint32_t* b) {
    asm volatile("mma.sync.aligned.m16n8k16.row.col.f32.bf16.bf16.f32 "
                 "{%0,%1,%2,%3}, {%4,%5,%6,%7}, {%8,%9}, {%0,%1,%2,%3};"
                 : "+f"(d[0]), "+f"(d[1]), "+f"(d[2]), "+f"(d[3])
                 : "r"(a[0]), "r"(a[1]), "r"(a[2]), "r"(a[3]), "r"(b[0]), "r"(b[1]));
}
__device__ __forceinline__ uint32_t pack_bf16x2(float lo, float hi) {
    uint32_t r;
    asm("cvt.rn.satfinite.bf16x2.f32 %0, %1, %2;" : "=r"(r) : "f"(hi), "f"(lo));
    return r;
}
__device__ __forceinline__ float ex2f(float x) {
    float r;
    asm("ex2.approx.ftz.f32 %0, %1;" : "=f"(r) : "f"(x));
    return r;
}

// ---------------- kernel 1: HMMA Q/K/V projection (+conv in y==3, zeroing) ----------------
__global__ void projconv_kernel(const float* __restrict__ x,
                                const float* __restrict__ Wq, const float* __restrict__ bq,
                                const float* __restrict__ Wk, const float* __restrict__ bk,
                                const float* __restrict__ Wv, const float* __restrict__ bv,
                                const float* __restrict__ cw, const float* __restrict__ cb) {
    extern __shared__ char psm[];
    const int which = blockIdx.y;
    const int tid = threadIdx.x;

    if (which == 3) {
        // zero accumulators used later in the stream
        if (blockIdx.x == 0) {
            if (tid < EDIM) g_final[tid] = 0.f;
            if (tid == 64) g_ticket = 0u;
        }

        // ---- conv 2x2 + sigmoid partial sums ----
        const float w00 = cw[0], w01 = cw[1], w10 = cw[2], w11 = cw[3];
        const float bias = cb[0];
        const int total = CONV_H2 * CONV_W2;

        float acc = 0.f;
        for (int n = blockIdx.x * 256 + tid; n < total; n += CONV_BLOCKS * 256) {
            const int i = n % CONV_H2;
            const int j = n / CONV_H2;
            const float z = w00 * x[j * EDIM + i]
                          + w01 * x[(j + 1) * EDIM + i]
                          + w10 * x[j * EDIM + i + 1]
                          + w11 * x[(j + 1) * EDIM + i + 1]
                          + bias;
            acc += 1.f / (1.f + __expf(-z));
        }
        float* red = (float*)psm;
        red[tid] = acc;
        __syncthreads();
        for (int s2 = 128; s2 > 0; s2 >>= 1) {
            if (tid < s2) red[tid] += red[tid + s2];
            __syncthreads();
        }
        if (tid == 0) g_sig[blockIdx.x] = red[0];
        return;
    }

    // ---- HMMA projection: 128 rows per CTA ----
    char* xb = psm;                     // [128][144B] bf16 rows
    char* wb = psm + PROJ_XB;           // [64][144B]  bf16 rows (W: rows=f, cols=e)
    float* bs = (float*)(psm + PROJ_XB + PROJ_WB);

    const float* W = (which == 0) ? Wq : (which == 1) ? Wk : Wv;
    const float* b = (which == 0) ? bq : (which == 1) ? bk : bv;
    __nv_bfloat16* dst = (which == 0) ? g_q : (which == 1) ? g_k : g_v;
    const float oscale = (which == 0) ? QSCALE : 1.0f;   // fold softmax scale+log2e into Q

    const int r0 = blockIdx.x * PROJ_ROWS;
    const uint32_t smb = smem_u32(psm);

    // stage x tile -> bf16 smem (8 floats -> 16B bf16 per group)
#pragma unroll
    for (int it = 0; it < 4; it++) {
        const int n = tid + it * 256;            // 1024 groups
        const int row = n >> 3, seg = n & 7;
        const float4 a0 = *(const float4*)&x[(r0 + row) * EDIM + seg * 8];
        const float4 a1 = *(const float4*)&x[(r0 + row) * EDIM + seg * 8 + 4];
        uint4 u;
        u.x = pack_bf16x2(a0.x, a0.y); u.y = pack_bf16x2(a0.z, a0.w);
        u.z = pack_bf16x2(a1.x, a1.y); u.w = pack_bf16x2(a1.z, a1.w);
        *(uint4*)(xb + row * ROWB + seg * 16) = u;
    }
    // stage W -> bf16 smem
#pragma unroll
    for (int it = 0; it < 2; it++) {
        const int n = tid + it * 256;            // 512 groups
        const int row = n >> 3, seg = n & 7;
        const float4 a0 = *(const float4*)&W[row * EDIM + seg * 8];
        const float4 a1 = *(const float4*)&W[row * EDIM + seg * 8 + 4];
        uint4 u;
        u.x = pack_bf16x2(a0.x, a0.y); u.y = pack_bf16x2(a0.z, a0.w);
        u.z = pack_bf16x2(a1.x, a1.y); u.w = pack_bf16x2(a1.z, a1.w);
        *(uint4*)(wb + row * ROWB + seg * 16) = u;
    }
    if (tid < EDIM) bs[tid] = b[tid];
    __syncthreads();

    const int wid = tid >> 5;
    const int lid = tid & 31;
    const int lr  = (lid & 7) + ((lid >> 3) & 1) * 8;
    const int lc  = ((lid >> 4) & 1) * 8;
    const int i2  = lid & 3;

    // A frags: 16 rows of x per warp
    uint32_t qa[4][4];
    {
        const uint32_t addrA = smb + (16 * wid + lr) * ROWB + lc * 2;
#pragma unroll
        for (int kc = 0; kc < 4; kc++) ldsm4(qa[kc], addrA + kc * 32);
    }

    // C frags init with bias (rows g and g+8 share column -> same bias)
    float acc[8][4];
#pragma unroll
    for (int nt = 0; nt < 8; nt++) {
        const float b0 = bs[8 * nt + 2 * i2];
        const float b1 = bs[8 * nt + 2 * i2 + 1];
        acc[nt][0] = b0; acc[nt][1] = b1; acc[nt][2] = b0; acc[nt][3] = b1;
    }

    // B frags from W via trans-ldmatrix (rows=f=k, cols=e=n)
    const uint32_t addrW = smb + PROJ_XB + lr * ROWB + lc * 2;
#pragma unroll
    for (int kc = 0; kc < 4; kc++) {
        uint32_t wf[8][2];
#pragma unroll
        for (int p = 0; p < 4; p++) ldsm4t(&wf[2 * p][0], addrW + kc * (16 * ROWB) + p * 32);
#pragma unroll
        for (int nt = 0; nt < 8; nt++) mma_bf16(acc[nt], qa[kc], wf[nt]);
    }

    // store packed bf16 results (Q pre-scaled by QSCALE in fp32 before rounding)
    const int g = lid >> 2;
    const int gr0 = r0 + 16 * wid + g;
    const int gr1 = gr0 + 8;
#pragma unroll
    for (int nt = 0; nt < 8; nt++) {
        const int e = 8 * nt + 2 * i2;
        *(uint32_t*)&dst[gr0 * EDIM + e] = pack_bf16x2(acc[nt][0] * oscale, acc[nt][1] * oscale);
        *(uint32_t*)&dst[gr1 * EDIM + e] = pack_bf16x2(acc[nt][2] * oscale, acc[nt][3] * oscale);
    }
}

// ---------------- async tile loader: 128 rows x 64 bf16, padded rows ----------------
__device__ __forceinline__ void load_part(uint32_t dst, const __nv_bfloat16* __restrict__ src,
                                          int row0, int tid) {
#pragma unroll
    for (int it = 0; it < 4; it++) {
        const int n = tid + it * 256;
        const int j = n >> 3, seg = n & 7;
        cp16(dst + j * ROWB + seg * 16, src + (row0 + j) * EDIM + seg * 8);
    }
}

// ---------------- kernel 2: HMMA flash attention (no-max softmax, split-K) ----------------
__global__ void __launch_bounds__(256, 1) fa_kernel() {
    extern __shared__ char sm[];
    const uint32_t smb = smem_u32(sm);
    const int tid = threadIdx.x;
    const int wid = tid >> 5;
    const int lid = tid & 31;
    const int rb = blockIdx.x >> 1;
    const int kh = blockIdx.x & 1;
    const int i0 = rb * BM;
    const int kbase = kh * KHALF;

    // lane offset patterns for ldmatrix address generation
    const int lr  = (lid & 7) + ((lid >> 3) & 1) * 8;   // A / V(trans) row pattern
    const int lc  = ((lid >> 4) & 1) * 8;               // A / V(trans) col pattern
    const int lr2 = (lid & 7) + ((lid >> 4) & 1) * 8;   // K(B) row pattern
    const int lc2 = ((lid >> 3) & 1) * 8;               // K(B) col pattern

    // ---- stage Q through smem, build persistent A-frags ----
#pragma unroll
    for (int it = 0; it < 4; it++) {
        const int n = tid + it * 256;
        const int j = n >> 3, seg = n & 7;
        *(uint4*)(sm + j * ROWB + seg * 16) = *(const uint4*)(g_q + (i0 + j) * EDIM + seg * 8);
    }
    __syncthreads();

    uint32_t qh[4][4];
    {
        const uint32_t addrA = smb + (16 * wid + lr) * ROWB + lc * 2;
#pragma unroll
        for (int kc = 0; kc < 4; kc++) ldsm4(qh[kc], addrA + kc * 32);
    }
    __syncthreads();

    // ---- prologue: prefetch tile 0 into buffer 0 ----
    load_part(smb + 0 * TILEB, g_k, kbase, tid);
    load_part(smb + 1 * TILEB, g_v, kbase, tid);
    CP_COMMIT();

    float Oacc[8][4];
#pragma unroll
    for (int i = 0; i < 8; i++)
#pragma unroll
        for (int j = 0; j < 4; j++) Oacc[i][j] = 0.f;
    float l0 = 0.f, l1 = 0.f;

    for (int t = 0; t < NTILE; t++) {
        CP_WAIT0();
        __syncthreads();

        if (t + 1 < NTILE) {  // prefetch next tile into other buffer
            const uint32_t nb = smb + ((t + 1) & 1) * 2 * TILEB;
            const int k0n = kbase + (t + 1) * BN;
            load_part(nb + 0 * TILEB, g_k, k0n, tid);
            load_part(nb + 1 * TILEB, g_v, k0n, tid);
            CP_COMMIT();
        }

        const uint32_t cb = smb + (t & 1) * 2 * TILEB;

        // ---- GEMM1: S(16x128 per warp) = Qs * K^T (Q pre-scaled: S in log2 domain) ----
        float sacc[16][4];
#pragma unroll
        for (int i = 0; i < 16; i++)
#pragma unroll
            for (int j = 0; j < 4; j++) sacc[i][j] = 0.f;

        const uint32_t addrK = cb + lr2 * ROWB + lc2 * 2;
#pragma unroll
        for (int kc = 0; kc < 4; kc++) {
            uint32_t kb[16][2];
#pragma unroll
            for (int p = 0; p < 8; p++) ldsm4(&kb[2 * p][0], addrK + p * (16 * ROWB) + kc * 32);
#pragma unroll
            for (int nt = 0; nt < 16; nt++) mma_bf16(sacc[nt], qh[kc], kb[nt]);
        }

        // ---- softmax epilogue (no max, no rescale): P = 2^S, bare EX2 ----
        uint32_t pa[8][4];
#pragma unroll
        for (int nt = 0; nt < 16; nt++) {
            const float p0 = ex2f(sacc[nt][0]);
            const float p1 = ex2f(sacc[nt][1]);
            const float p2 = ex2f(sacc[nt][2]);
            const float p3 = ex2f(sacc[nt][3]);
            l0 += p0 + p1;
            l1 += p2 + p3;
            pa[nt >> 1][(nt & 1) * 2 + 0] = pack_bf16x2(p0, p1);
            pa[nt >> 1][(nt & 1) * 2 + 1] = pack_bf16x2(p2, p3);
        }

        // ---- GEMM2: O(16x64 per warp) += P * V ----
        const uint32_t addrV = cb + TILEB + lr * ROWB + lc * 2;
#pragma unroll
        for (int ks = 0; ks < 8; ks++) {
            uint32_t vb[8][2];
#pragma unroll
            for (int p = 0; p < 4; p++) ldsm4t(&vb[2 * p][0], addrV + ks * (16 * ROWB) + p * 32);
#pragma unroll
            for (int nt = 0; nt < 8; nt++) mma_bf16(Oacc[nt], pa[ks], vb[nt]);
        }
    }

    // ---- writeback: O partials + row-sum partials ----
    const int g  = lid >> 2;
    const int i2 = lid & 3;
    const int r0 = 16 * wid + g;
    const int r1 = r0 + 8;
#pragma unroll
    for (int nt = 0; nt < 8; nt++) {
        const int e = 8 * nt + 2 * i2;
        *(float2*)&g_O[blockIdx.x][r0][e] = make_float2(Oacc[nt][0], Oacc[nt][1]);
        *(float2*)&g_O[blockIdx.x][r1][e] = make_float2(Oacc[nt][2], Oacc[nt][3]);
    }
    l0 += __shfl_xor_sync(0xFFFFFFFF, l0, 1);
    l0 += __shfl_xor_sync(0xFFFFFFFF, l0, 2);
    l1 += __shfl_xor_sync(0xFFFFFFFF, l1, 1);
    l1 += __shfl_xor_sync(0xFFFFFFFF, l1, 2);
    if (i2 == 0) {
        g_l[blockIdx.x][r0] = l0;
        g_l[blockIdx.x][r1] = l1;
    }
}

// ---------------- kernel 3: combine split-K partials + (last CTA) final projection ----------------
__global__ void combine_kernel(const float* __restrict__ Wp,
                               const float* __restrict__ bp,
                               float* __restrict__ out) {
    __shared__ float pool[EDIM];
    __shared__ unsigned int rank;
    const int rb  = blockIdx.x;       // 0..63
    const int grp = blockIdx.y;       // 0..7 (16 rows each)
    const int tid = threadIdx.x;      // 256
    const int e = tid & 63;
    const int rg = tid >> 6;          // 0..3
    if (tid < EDIM) pool[tid] = 0.f;
    __syncthreads();

    float acc = 0.f;
#pragma unroll
    for (int jj = 0; jj < 4; jj++) {
        const int row = grp * 16 + rg * 4 + jj;
        const float la = g_l[2 * rb][row], lb = g_l[2 * rb + 1][row];
        const float inv = 1.f / (la + lb);
        acc += (g_O[2 * rb][row][e] + g_O[2 * rb + 1][row][e]) * inv;
    }
    atomicAdd(&pool[e], acc);
    __syncthreads();
    if (tid < EDIM) atomicAdd(&g_final[tid], pool[tid]);

    // ---- last-CTA final projection (atomic ticket) ----
    __threadfence();
    if (tid == 0) rank = atomicAdd(&g_ticket, 1u);
    __syncthreads();
    if (rank == NCOMBINE - 1) {
        __threadfence();
        __shared__ float red[256];
        __shared__ float ps[EDIM];
        red[tid] = (tid < CONV_BLOCKS) ? g_sig[tid] : 0.f;
        if (tid < EDIM) ps[tid] = g_final[tid];
        __syncthreads();
        for (int s2 = 128; s2 > 0; s2 >>= 1) {
            if (tid < s2) red[tid] += red[tid + s2];
            __syncthreads();
        }
        if (tid < 4) {
            const float cf = red[0] / (float)(CONV_H2 * CONV_W2);
            const float sc = cf * (1.f / (float)S_LEN);
            float o = bp[tid];
#pragma unroll 8
            for (int k = 0; k < EDIM; k++)
                o += ps[k] * sc * Wp[k * 4 + tid];
            out[tid] = o;
        }
    }
}

// ---------------- launcher ----------------
extern "C" void kernel_launch(void* const* d_in, const int* in_sizes, int n_in,
                              void* d_out, int out_size) {
    const float* x      = (const float*)d_in[0];
    const float* conv_w = (const float*)d_in[1];
    const float* conv_b = (const float*)d_in[2];
    const float* Wq     = (const float*)d_in[3];
    const float* bq     = (const float*)d_in[4];
    const float* Wk     = (const float*)d_in[5];
    const float* bk     = (const float*)d_in[6];
    const float* Wv     = (const float*)d_in[7];
    const float* bv     = (const float*)d_in[8];
    const float* Wp     = (const float*)d_in[9];
    const float* bp     = (const float*)d_in[10];
    float* out = (float*)d_out;

    cudaFuncSetAttribute(fa_kernel, cudaFuncAttributeMaxDynamicSharedMemorySize, SMEM_TOTAL);
    cudaFuncSetAttribute(projconv_kernel, cudaFuncAttributeMaxDynamicSharedMemorySize, PROJ_SMEM);

    projconv_kernel<<<dim3(S_LEN / PROJ_ROWS, 4), 256, PROJ_SMEM>>>(
        x, Wq, bq, Wk, bk, Wv, bv, conv_w, conv_b);
    fa_kernel<<<NCTA, 256, SMEM_TOTAL>>>();
    combine_kernel<<<dim3(NRB, 8), 256>>>(Wp, bp, out);
}

// round 17
// speedup vs baseline: 1.5245x; 1.0290x over previous
#include <cuda_runtime.h>
#include <cuda_bf16.h>
#include <cstdint>

#define S_LEN 8192
#define EDIM  64
#define BM    128
#define BN    128
#define NRB   (S_LEN / BM)      // 64 row blocks
#define NCTA  (NRB * 2)         // 128 CTAs (x2 key halves)
#define KHALF (S_LEN / 2)       // 4096
#define NTILE (KHALF / BN)      // 32 key tiles per CTA
#define CONV_BLOCKS 64
#define CONV_W2 (S_LEN - 1)
#define CONV_H2 (EDIM - 1)
#define NCOMBINE (NRB * 8)      // 512 combine CTAs

#define ROWB  144               // padded row stride bytes (64 bf16 + 8 pad)
#define TILEB (128 * ROWB)      // 18432 B per tile buffer
#define SMEM_TOTAL (4 * TILEB)  // 73728 B (double-buffered K,V)

// Q pre-scale: 0.125 (1/sqrt(E)) * log2(e), so P = exp2(S') with S' = Qs K^T
#define QSCALE 0.18033688f

// proj kernel smem: xb[128][144B] bf16 + wb[64][144B] bf16 + bs[64] f32
#define PROJ_ROWS 128
#define PROJ_XB   (PROJ_ROWS * ROWB)          // 18432
#define PROJ_WB   (EDIM * ROWB)               // 9216
#define PROJ_SMEM (PROJ_XB + PROJ_WB + 256)   // 27904 B

// ---------------- device scratch ----------------
__device__ __nv_bfloat16 g_q[S_LEN * EDIM];
__device__ __nv_bfloat16 g_k[S_LEN * EDIM];
__device__ __nv_bfloat16 g_v[S_LEN * EDIM];
__device__ float g_O[NCTA][BM][EDIM];
__device__ float g_l[NCTA][BM];
__device__ float g_final[EDIM];
__device__ float g_sig[CONV_BLOCKS];
__device__ unsigned int g_ticket;

// ---------------- PTX helpers (generic sm_80+ features only) ----------------
__device__ __forceinline__ uint32_t smem_u32(const void* p) {
    uint32_t a;
    asm("{ .reg .u64 t; cvta.to.shared.u64 t, %1; cvt.u32.u64 %0, t; }" : "=r"(a) : "l"(p));
    return a;
}
__device__ __forceinline__ void cp16(uint32_t dst, const void* src) {
    asm volatile("cp.async.cg.shared.global [%0], [%1], 16;" :: "r"(dst), "l"(src));
}
#define CP_COMMIT() asm volatile("cp.async.commit_group;" ::: "memory")
#define CP_WAIT0()  asm volatile("cp.async.wait_group 0;" ::: "memory")

__device__ __forceinline__ void ldsm4(uint32_t* r, uint32_t a) {
    asm volatile("ldmatrix.sync.aligned.m8n8.x4.shared.b16 {%0,%1,%2,%3}, [%4];"
                 : "=r"(r[0]), "=r"(r[1]), "=r"(r[2]), "=r"(r[3]) : "r"(a));
}
__device__ __forceinline__ void ldsm4t(uint32_t* r, uint32_t a) {
    asm volatile("ldmatrix.sync.aligned.m8n8.x4.trans.shared.b16 {%0,%1,%2,%3}, [%4];"
                 : "=r"(r[0]), "=r"(r[1]), "=r"(r[2]), "=r"(r[3]) : "r"(a));
}
__device__ __forceinline__ void mma_bf16(float* d, const uint32_t* a, const uint32_t* b) {
    asm volatile("mma.sync.aligned.m16n8k16.row.col.f32.bf16.bf16.f32 "
                 "{%0,%1,%2,%3}, {%4,%5,%6,%7}, {%8,%9}, {%0,%1,%2,%3};"
                 : "+f"(d[0]), "+f"(d[1]), "+f"(d[2]), "+f"(d[3])
                 : "r"(a[0]), "r"(a[1]), "r"(a[2]), "r"(a[3]), "r"(b[0]), "r"(b[1]));
}
__device__ __forceinline__ uint32_t pack_bf16x2(float lo, float hi) {
    uint32_t r;
    asm("cvt.rn.satfinite.bf16x2.f32 %0, %1, %2;" : "=r"(r) : "f"(hi), "f"(lo));
    return r;
}
__device__ __forceinline__ float ex2f(float x) {
    float r;
    asm("ex2.approx.ftz.f32 %0, %1;" : "=f"(r) : "f"(x));
    return r;
}

// ---------------- kernel 1: HMMA Q/K/V projection (+conv in y==3, zeroing) ----------------
__global__ void projconv_kernel(const float* __restrict__ x,
                                const float* __restrict__ Wq, const float* __restrict__ bq,
                                const float* __restrict__ Wk, const float* __restrict__ bk,
                                const float* __restrict__ Wv, const float* __restrict__ bv,
                                const float* __restrict__ cw, const float* __restrict__ cb) {
    extern __shared__ char psm[];
    const int which = blockIdx.y;
    const int tid = threadIdx.x;

    if (which == 3) {
        // zero accumulators used later in the stream
        if (blockIdx.x == 0) {
            if (tid < EDIM) g_final[tid] = 0.f;
            if (tid == 64) g_ticket = 0u;
        }

        // ---- conv 2x2 + sigmoid partial sums ----
        const float w00 = cw[0], w01 = cw[1], w10 = cw[2], w11 = cw[3];
        const float bias = cb[0];
        const int total = CONV_H2 * CONV_W2;

        float acc = 0.f;
        for (int n = blockIdx.x * 256 + tid; n < total; n += CONV_BLOCKS * 256) {
            const int i = n % CONV_H2;
            const int j = n / CONV_H2;
            const float z = w00 * x[j * EDIM + i]
                          + w01 * x[(j + 1) * EDIM + i]
                          + w10 * x[j * EDIM + i + 1]
                          + w11 * x[(j + 1) * EDIM + i + 1]
                          + bias;
            acc += 1.f / (1.f + __expf(-z));
        }
        float* red = (float*)psm;
        red[tid] = acc;
        __syncthreads();
        for (int s2 = 128; s2 > 0; s2 >>= 1) {
            if (tid < s2) red[tid] += red[tid + s2];
            __syncthreads();
        }
        if (tid == 0) g_sig[blockIdx.x] = red[0];
        return;
    }

    // ---- HMMA projection: 128 rows per CTA ----
    char* xb = psm;                     // [128][144B] bf16 rows
    char* wb = psm + PROJ_XB;           // [64][144B]  bf16 rows (W: rows=f, cols=e)
    float* bs = (float*)(psm + PROJ_XB + PROJ_WB);

    const float* W = (which == 0) ? Wq : (which == 1) ? Wk : Wv;
    const float* b = (which == 0) ? bq : (which == 1) ? bk : bv;
    __nv_bfloat16* dst = (which == 0) ? g_q : (which == 1) ? g_k : g_v;
    const float oscale = (which == 0) ? QSCALE : 1.0f;   // fold softmax scale+log2e into Q

    const int r0 = blockIdx.x * PROJ_ROWS;
    const uint32_t smb = smem_u32(psm);

    // stage x tile -> bf16 smem (8 floats -> 16B bf16 per group)
#pragma unroll
    for (int it = 0; it < 4; it++) {
        const int n = tid + it * 256;            // 1024 groups
        const int row = n >> 3, seg = n & 7;
        const float4 a0 = *(const float4*)&x[(r0 + row) * EDIM + seg * 8];
        const float4 a1 = *(const float4*)&x[(r0 + row) * EDIM + seg * 8 + 4];
        uint4 u;
        u.x = pack_bf16x2(a0.x, a0.y); u.y = pack_bf16x2(a0.z, a0.w);
        u.z = pack_bf16x2(a1.x, a1.y); u.w = pack_bf16x2(a1.z, a1.w);
        *(uint4*)(xb + row * ROWB + seg * 16) = u;
    }
    // stage W -> bf16 smem
#pragma unroll
    for (int it = 0; it < 2; it++) {
        const int n = tid + it * 256;            // 512 groups
        const int row = n >> 3, seg = n & 7;
        const float4 a0 = *(const float4*)&W[row * EDIM + seg * 8];
        const float4 a1 = *(const float4*)&W[row * EDIM + seg * 8 + 4];
        uint4 u;
        u.x = pack_bf16x2(a0.x, a0.y); u.y = pack_bf16x2(a0.z, a0.w);
        u.z = pack_bf16x2(a1.x, a1.y); u.w = pack_bf16x2(a1.z, a1.w);
        *(uint4*)(wb + row * ROWB + seg * 16) = u;
    }
    if (tid < EDIM) bs[tid] = b[tid];
    __syncthreads();

    const int wid = tid >> 5;
    const int lid = tid & 31;
    const int lr  = (lid & 7) + ((lid >> 3) & 1) * 8;
    const int lc  = ((lid >> 4) & 1) * 8;
    const int i2  = lid & 3;

    // A frags: 16 rows of x per warp
    uint32_t qa[4][4];
    {
        const uint32_t addrA = smb + (16 * wid + lr) * ROWB + lc * 2;
#pragma unroll
        for (int kc = 0; kc < 4; kc++) ldsm4(qa[kc], addrA + kc * 32);
    }

    // C frags init with bias (rows g and g+8 share column -> same bias)
    float acc[8][4];
#pragma unroll
    for (int nt = 0; nt < 8; nt++) {
        const float b0 = bs[8 * nt + 2 * i2];
        const float b1 = bs[8 * nt + 2 * i2 + 1];
        acc[nt][0] = b0; acc[nt][1] = b1; acc[nt][2] = b0; acc[nt][3] = b1;
    }

    // B frags from W via trans-ldmatrix (rows=f=k, cols=e=n)
    const uint32_t addrW = smb + PROJ_XB + lr * ROWB + lc * 2;
#pragma unroll
    for (int kc = 0; kc < 4; kc++) {
        uint32_t wf[8][2];
#pragma unroll
        for (int p = 0; p < 4; p++) ldsm4t(&wf[2 * p][0], addrW + kc * (16 * ROWB) + p * 32);
#pragma unroll
        for (int nt = 0; nt < 8; nt++) mma_bf16(acc[nt], qa[kc], wf[nt]);
    }

    // store packed bf16 results (Q pre-scaled by QSCALE in fp32 before rounding)
    const int g = lid >> 2;
    const int gr0 = r0 + 16 * wid + g;
    const int gr1 = gr0 + 8;
#pragma unroll
    for (int nt = 0; nt < 8; nt++) {
        const int e = 8 * nt + 2 * i2;
        *(uint32_t*)&dst[gr0 * EDIM + e] = pack_bf16x2(acc[nt][0] * oscale, acc[nt][1] * oscale);
        *(uint32_t*)&dst[gr1 * EDIM + e] = pack_bf16x2(acc[nt][2] * oscale, acc[nt][3] * oscale);
    }
}

// ---------------- async tile loader: 128 rows x 64 bf16, padded rows ----------------
__device__ __forceinline__ void load_part(uint32_t dst, const __nv_bfloat16* __restrict__ src,
                                          int row0, int tid) {
#pragma unroll
    for (int it = 0; it < 4; it++) {
        const int n = tid + it * 256;
        const int j = n >> 3, seg = n & 7;
        cp16(dst + j * ROWB + seg * 16, src + (row0 + j) * EDIM + seg * 8);
    }
}

// ---------------- kernel 2: HMMA flash attention (no-max softmax, split-K) ----------------
__global__ void __launch_bounds__(256, 1) fa_kernel() {
    extern __shared__ char sm[];
    const uint32_t smb = smem_u32(sm);
    const int tid = threadIdx.x;
    const int wid = tid >> 5;
    const int lid = tid & 31;
    const int rb = blockIdx.x >> 1;
    const int kh = blockIdx.x & 1;
    const int i0 = rb * BM;
    const int kbase = kh * KHALF;

    // lane offset patterns for ldmatrix address generation
    const int lr  = (lid & 7) + ((lid >> 3) & 1) * 8;   // A / V(trans) row pattern
    const int lc  = ((lid >> 4) & 1) * 8;               // A / V(trans) col pattern
    const int lr2 = (lid & 7) + ((lid >> 4) & 1) * 8;   // K(B) row pattern
    const int lc2 = ((lid >> 3) & 1) * 8;               // K(B) col pattern

    // constant ones B-fragment (column n=0 of an 8-wide tile is all 1.0 bf16)
    uint32_t b_ones[2];
    b_ones[0] = b_ones[1] = ((lid >> 2) == 0) ? 0x3F803F80u : 0u;

    // ---- stage Q through smem, build persistent A-frags ----
#pragma unroll
    for (int it = 0; it < 4; it++) {
        const int n = tid + it * 256;
        const int j = n >> 3, seg = n & 7;
        *(uint4*)(sm + j * ROWB + seg * 16) = *(const uint4*)(g_q + (i0 + j) * EDIM + seg * 8);
    }
    __syncthreads();

    uint32_t qh[4][4];
    {
        const uint32_t addrA = smb + (16 * wid + lr) * ROWB + lc * 2;
#pragma unroll
        for (int kc = 0; kc < 4; kc++) ldsm4(qh[kc], addrA + kc * 32);
    }
    __syncthreads();

    // ---- prologue: prefetch tile 0 into buffer 0 ----
    load_part(smb + 0 * TILEB, g_k, kbase, tid);
    load_part(smb + 1 * TILEB, g_v, kbase, tid);
    CP_COMMIT();

    float Oacc[8][4];
#pragma unroll
    for (int i = 0; i < 8; i++)
#pragma unroll
        for (int j = 0; j < 4; j++) Oacc[i][j] = 0.f;
    float lfrag[4] = {0.f, 0.f, 0.f, 0.f};   // row sums accumulate in column 0 via ones-MMA

    for (int t = 0; t < NTILE; t++) {
        CP_WAIT0();
        __syncthreads();

        if (t + 1 < NTILE) {  // prefetch next tile into other buffer
            const uint32_t nb = smb + ((t + 1) & 1) * 2 * TILEB;
            const int k0n = kbase + (t + 1) * BN;
            load_part(nb + 0 * TILEB, g_k, k0n, tid);
            load_part(nb + 1 * TILEB, g_v, k0n, tid);
            CP_COMMIT();
        }

        const uint32_t cb = smb + (t & 1) * 2 * TILEB;

        // ---- GEMM1: S(16x128 per warp) = Qs * K^T (Q pre-scaled: S in log2 domain) ----
        float sacc[16][4];
#pragma unroll
        for (int i = 0; i < 16; i++)
#pragma unroll
            for (int j = 0; j < 4; j++) sacc[i][j] = 0.f;

        const uint32_t addrK = cb + lr2 * ROWB + lc2 * 2;
#pragma unroll
        for (int kc = 0; kc < 4; kc++) {
            uint32_t kb[16][2];
#pragma unroll
            for (int p = 0; p < 8; p++) ldsm4(&kb[2 * p][0], addrK + p * (16 * ROWB) + kc * 32);
#pragma unroll
            for (int nt = 0; nt < 16; nt++) mma_bf16(sacc[nt], qh[kc], kb[nt]);
        }

        // ---- softmax epilogue (no max, no rescale): P = 2^S, bare EX2, no scalar sums ----
        uint32_t pa[8][4];
#pragma unroll
        for (int nt = 0; nt < 16; nt++) {
            const float p0 = ex2f(sacc[nt][0]);
            const float p1 = ex2f(sacc[nt][1]);
            const float p2 = ex2f(sacc[nt][2]);
            const float p3 = ex2f(sacc[nt][3]);
            pa[nt >> 1][(nt & 1) * 2 + 0] = pack_bf16x2(p0, p1);
            pa[nt >> 1][(nt & 1) * 2 + 1] = pack_bf16x2(p2, p3);
        }

        // ---- GEMM2: O(16x64 per warp) += P * V ; l += P * ones (tensor-pipe row sums) ----
        const uint32_t addrV = cb + TILEB + lr * ROWB + lc * 2;
#pragma unroll
        for (int ks = 0; ks < 8; ks++) {
            uint32_t vb[8][2];
#pragma unroll
            for (int p = 0; p < 4; p++) ldsm4t(&vb[2 * p][0], addrV + ks * (16 * ROWB) + p * 32);
#pragma unroll
            for (int nt = 0; nt < 8; nt++) mma_bf16(Oacc[nt], pa[ks], vb[nt]);
            mma_bf16(lfrag, pa[ks], b_ones);
        }
    }

    // ---- writeback: O partials + row-sum partials (lfrag col 0 -> lanes i2==0) ----
    const int g  = lid >> 2;
    const int i2 = lid & 3;
    const int r0 = 16 * wid + g;
    const int r1 = r0 + 8;
#pragma unroll
    for (int nt = 0; nt < 8; nt++) {
        const int e = 8 * nt + 2 * i2;
        *(float2*)&g_O[blockIdx.x][r0][e] = make_float2(Oacc[nt][0], Oacc[nt][1]);
        *(float2*)&g_O[blockIdx.x][r1][e] = make_float2(Oacc[nt][2], Oacc[nt][3]);
    }
    if (i2 == 0) {
        g_l[blockIdx.x][r0] = lfrag[0];
        g_l[blockIdx.x][r1] = lfrag[2];
    }
}

// ---------------- kernel 3: combine split-K partials + (last CTA) final projection ----------------
__global__ void combine_kernel(const float* __restrict__ Wp,
                               const float* __restrict__ bp,
                               float* __restrict__ out) {
    __shared__ float pool[EDIM];
    __shared__ unsigned int rank;
    const int rb  = blockIdx.x;       // 0..63
    const int grp = blockIdx.y;       // 0..7 (16 rows each)
    const int tid = threadIdx.x;      // 256
    const int e = tid & 63;
    const int rg = tid >> 6;          // 0..3
    if (tid < EDIM) pool[tid] = 0.f;
    __syncthreads();

    float acc = 0.f;
#pragma unroll
    for (int jj = 0; jj < 4; jj++) {
        const int row = grp * 16 + rg * 4 + jj;
        const float la = g_l[2 * rb][row], lb = g_l[2 * rb + 1][row];
        const float inv = 1.f / (la + lb);
        acc += (g_O[2 * rb][row][e] + g_O[2 * rb + 1][row][e]) * inv;
    }
    atomicAdd(&pool[e], acc);
    __syncthreads();
    if (tid < EDIM) atomicAdd(&g_final[tid], pool[tid]);

    // ---- last-CTA final projection (atomic ticket) ----
    __threadfence();
    if (tid == 0) rank = atomicAdd(&g_ticket, 1u);
    __syncthreads();
    if (rank == NCOMBINE - 1) {
        __threadfence();
        __shared__ float red[256];
        __shared__ float ps[EDIM];
        red[tid] = (tid < CONV_BLOCKS) ? g_sig[tid] : 0.f;
        if (tid < EDIM) ps[tid] = g_final[tid];
        __syncthreads();
        for (int s2 = 128; s2 > 0; s2 >>= 1) {
            if (tid < s2) red[tid] += red[tid + s2];
            __syncthreads();
        }
        if (tid < 4) {
            const float cf = red[0] / (float)(CONV_H2 * CONV_W2);
            const float sc = cf * (1.f / (float)S_LEN);
            float o = bp[tid];
#pragma unroll 8
            for (int k = 0; k < EDIM; k++)
                o += ps[k] * sc * Wp[k * 4 + tid];
            out[tid] = o;
        }
    }
}

// ---------------- launcher ----------------
extern "C" void kernel_launch(void* const* d_in, const int* in_sizes, int n_in,
                              void* d_out, int out_size) {
    const float* x      = (const float*)d_in[0];
    const float* conv_w = (const float*)d_in[1];
    const float* conv_b = (const float*)d_in[2];
    const float* Wq     = (const float*)d_in[3];
    const float* bq     = (const float*)d_in[4];
    const float* Wk     = (const float*)d_in[5];
    const float* bk     = (const float*)d_in[6];
    const float* Wv     = (const float*)d_in[7];
    const float* bv     = (const float*)d_in[8];
    const float* Wp     = (const float*)d_in[9];
    const float* bp     = (const float*)d_in[10];
    float* out = (float*)d_out;

    cudaFuncSetAttribute(fa_kernel, cudaFuncAttributeMaxDynamicSharedMemorySize, SMEM_TOTAL);
    cudaFuncSetAttribute(projconv_kernel, cudaFuncAttributeMaxDynamicSharedMemorySize, PROJ_SMEM);

    projconv_kernel<<<dim3(S_LEN / PROJ_ROWS, 4), 256, PROJ_SMEM>>>(
        x, Wq, bq, Wk, bk, Wv, bv, conv_w, conv_b);
    fa_kernel<<<NCTA, 256, SMEM_TOTAL>>>();
    combine_kernel<<<dim3(NRB, 8), 256>>>(Wp, bp, out);
}